// round 9
// baseline (speedup 1.0000x reference)
#include <cuda_runtime.h>
#include <float.h>

// fm [B=4, C=256, H=50, W=50] f32, rois [R=300,5] f32 -> out [R,256,7,7] f32.
#define PH 7
#define PW 7
#define B_ 4
#define C_ 256
#define H_ 50
#define W_ 50
#define HW (H_ * W_)

// channels-last scratch: fmT[b][y][x][c]  (10.24 MB)
__device__ float g_fmT[B_ * HW * C_];

__device__ __forceinline__ int clampi(int v, int lo, int hi) {
    return min(max(v, lo), hi);
}

// [256, 2500] -> [2500, 256] transpose per batch, 32x32 tiles. (validated)
__global__ __launch_bounds__(256) void transpose_kernel(
        const float* __restrict__ in) {
    __shared__ float tile[32][33];
    const int b   = blockIdx.z;
    const int hw0 = blockIdx.x * 32;
    const int c0  = blockIdx.y * 32;
    const int tx  = threadIdx.x;          // 32
    const int ty  = threadIdx.y;          // 8

    #pragma unroll
    for (int j = 0; j < 4; ++j) {
        int cl = ty + j * 8;
        int hw = hw0 + tx;
        if (hw < HW)
            tile[cl][tx] = in[(size_t)(b * C_ + c0 + cl) * HW + hw];
    }
    __syncthreads();
    #pragma unroll
    for (int j = 0; j < 4; ++j) {
        int hwl = ty + j * 8;
        int hw  = hw0 + hwl;
        if (hw < HW)
            g_fmT[(size_t)(b * HW + hw) * C_ + c0 + tx] = tile[tx][hwl];
    }
}

// Block = (ph, roi). Thread = float2 channel-pair. Each strip column is
// loaded ONCE (column-max in registers), then folded into 7 bin
// accumulators with unrolled predicated updates. Output staged in smem,
// written directly in final NCHW layout (no reorder kernel).
__global__ __launch_bounds__(128) void roi_pool_kernel(
        const float* __restrict__ rois, float* __restrict__ out) {
    __shared__ float so[C_ * PW];          // [c*7 + pw], 7 KB

    const int ph = blockIdx.x;
    const int r  = blockIdx.y;
    const int cp = threadIdx.x;            // channel pair 0..127

    // ---- ROI box (block-uniform; jnp.round == rintf under RN) ----
    const float* rp = rois + r * 5;
    const int b  = (int)__ldg(rp + 4);                 // float truncation
    int x0 = clampi((int)rintf(__ldg(rp + 0)), 0, W_ - 1);
    int x1 = clampi((int)rintf(__ldg(rp + 2)), 0, W_ - 1);
    int y0 = clampi((int)rintf(__ldg(rp + 1)), 0, H_ - 1);
    int y1 = clampi((int)rintf(__ldg(rp + 3)), 0, H_ - 1);
    x1 = max(x1, x0 + 1);                  // edges may reach 50; reads <= 49
    y1 = max(y1, y0 + 1);
    const int w = x1 - x0;                 // 1..49
    const int h = y1 - y0;

    const int hs = y0 + (ph * h) / PH;
    const int he = y0 + ((ph + 1) * h + PH - 1) / PH;  // ceil
    const int sh = he - hs;                // 1..8

    int wsr[PW], wer[PW];                  // bin edges relative to x0
    #pragma unroll
    for (int i = 0; i < PW; ++i) {
        wsr[i] = (i * w) / PW;
        wer[i] = ((i + 1) * w + PW - 1) / PW;
    }

    float2 m[PW];
    #pragma unroll
    for (int i = 0; i < PW; ++i) m[i] = make_float2(-FLT_MAX, -FLT_MAX);

    const float* base = g_fmT + ((size_t)b * HW + hs * W_ + x0) * C_ + 2 * cp;

    int x = 0;
    for (; x + 1 < w; x += 2) {            // two independent column chains
        const float* p0 = base + (size_t)x * C_;
        const float* p1 = p0 + C_;
        float2 ca = make_float2(-FLT_MAX, -FLT_MAX);
        float2 cb = make_float2(-FLT_MAX, -FLT_MAX);
        for (int y = 0; y < sh; ++y) {
            float2 a = __ldg((const float2*)(p0 + (size_t)y * (W_ * C_)));
            float2 d = __ldg((const float2*)(p1 + (size_t)y * (W_ * C_)));
            ca.x = fmaxf(ca.x, a.x);  ca.y = fmaxf(ca.y, a.y);
            cb.x = fmaxf(cb.x, d.x);  cb.y = fmaxf(cb.y, d.y);
        }
        #pragma unroll
        for (int pw = 0; pw < PW; ++pw) {
            if (x >= wsr[pw] && x < wer[pw]) {
                m[pw].x = fmaxf(m[pw].x, ca.x);
                m[pw].y = fmaxf(m[pw].y, ca.y);
            }
            if (x + 1 >= wsr[pw] && x + 1 < wer[pw]) {
                m[pw].x = fmaxf(m[pw].x, cb.x);
                m[pw].y = fmaxf(m[pw].y, cb.y);
            }
        }
    }
    if (x < w) {                           // tail column
        const float* p0 = base + (size_t)x * C_;
        float2 ca = make_float2(-FLT_MAX, -FLT_MAX);
        for (int y = 0; y < sh; ++y) {
            float2 a = __ldg((const float2*)(p0 + (size_t)y * (W_ * C_)));
            ca.x = fmaxf(ca.x, a.x);  ca.y = fmaxf(ca.y, a.y);
        }
        #pragma unroll
        for (int pw = 0; pw < PW; ++pw) {
            if (x >= wsr[pw] && x < wer[pw]) {
                m[pw].x = fmaxf(m[pw].x, ca.x);
                m[pw].y = fmaxf(m[pw].y, ca.y);
            }
        }
    }

    // stage results: channels 2cp and 2cp+1, 7 bins each
    #pragma unroll
    for (int pw = 0; pw < PW; ++pw) {
        so[(2 * cp) * PW + pw]     = m[pw].x;
        so[(2 * cp + 1) * PW + pw] = m[pw].y;
    }
    __syncthreads();

    // write out[r][c][ph][pw]: linear smem read, 7-float runs per channel
    float* ob = out + (size_t)r * (C_ * PH * PW) + ph * PW;
    #pragma unroll
    for (int i = cp; i < C_ * PW; i += 128) {
        int c  = i / PW;
        int pw = i - c * PW;
        ob[c * (PH * PW) + pw] = so[i];
    }
}

extern "C" void kernel_launch(void* const* d_in, const int* in_sizes, int n_in,
                              void* d_out, int out_size) {
    const float* fm   = (const float*)d_in[0];
    const float* rois = (const float*)d_in[1];
    float* out = (float*)d_out;

    int R = in_sizes[1] / 5;               // 300

    dim3 tgrid((HW + 31) / 32, C_ / 32, B_);   // 79 x 8 x 4
    transpose_kernel<<<tgrid, dim3(32, 8)>>>(fm);

    dim3 pgrid(PH, R);                     // 7 x 300
    roi_pool_kernel<<<pgrid, 128>>>(rois, out);
}

// round 10
// speedup vs baseline: 1.1976x; 1.1976x over previous
#include <cuda_runtime.h>
#include <float.h>

// fm [B=4, C=256, H=50, W=50] f32, rois [R=300,5] f32 -> out [R,256,7,7] f32.
#define PH 7
#define PW 7
#define B_ 4
#define C_ 256
#define H_ 50
#define W_ 50
#define HW (H_ * W_)

// channels-last scratch: fmT[b][y][x][c]  (10.24 MB)
__device__ float g_fmT[B_ * HW * C_];

__device__ __forceinline__ int clampi(int v, int lo, int hi) {
    return min(max(v, lo), hi);
}

// [256, 2500] -> [2500, 256] transpose per batch, 32c x 64hw tiles,
// 8 independent loads + 8 independent stores per thread (ILP x2 vs R8).
__global__ __launch_bounds__(256) void transpose_kernel(
        const float* __restrict__ in) {
    __shared__ float tile[32][65];        // [c][hw], conflict-free both ways
    const int b   = blockIdx.z;
    const int hw0 = blockIdx.x * 64;
    const int c0  = blockIdx.y * 32;
    const int tx  = threadIdx.x;          // 32
    const int ty  = threadIdx.y;          // 8

    #pragma unroll
    for (int j = 0; j < 4; ++j) {
        const int cl = ty + j * 8;
        const float* src = in + (size_t)(b * C_ + c0 + cl) * HW;
        int hw = hw0 + tx;
        if (hw < HW)      tile[cl][tx]      = src[hw];
        hw = hw0 + 32 + tx;
        if (hw < HW)      tile[cl][tx + 32] = src[hw];
    }
    __syncthreads();
    #pragma unroll
    for (int j = 0; j < 8; ++j) {
        const int hwl = ty + j * 8;
        const int hw  = hw0 + hwl;
        if (hw < HW)
            g_fmT[(size_t)(b * HW + hw) * C_ + c0 + tx] = tile[tx][hwl];
    }
}

// Block = (ph, roi, 64-channel group): 8400 short uniform blocks.
// Warp = pw bin, lane = float2 channel-pair. Per-thread: ~12 independent
// dense float2 loads (one bin, 64 channels). Results staged in smem and
// written directly in NCHW (7-float runs) -- no reorder kernel.
__global__ __launch_bounds__(224) void roi_pool_kernel(
        const float* __restrict__ rois, float* __restrict__ out) {
    __shared__ float so[64 * PW];          // [c_local*7 + pw]

    const int ph  = blockIdx.x;
    const int r   = blockIdx.y;
    const int cg  = blockIdx.z;            // 0..3 (64 channels each)
    const int lane = threadIdx.x & 31;
    const int pw   = threadIdx.x >> 5;     // 0..6

    // ---- ROI box (block-uniform; jnp.round == rintf under RN) ----
    const float* rp = rois + r * 5;
    const int b  = (int)__ldg(rp + 4);                 // float truncation
    int x0 = clampi((int)rintf(__ldg(rp + 0)), 0, W_ - 1);
    int x1 = clampi((int)rintf(__ldg(rp + 2)), 0, W_ - 1);
    int y0 = clampi((int)rintf(__ldg(rp + 1)), 0, H_ - 1);
    int y1 = clampi((int)rintf(__ldg(rp + 3)), 0, H_ - 1);
    x1 = max(x1, x0 + 1);                  // edges may reach 50; reads <= 49
    y1 = max(y1, y0 + 1);
    const int w = x1 - x0;                 // 1..49
    const int h = y1 - y0;

    const int hs = y0 + (ph * h) / PH;
    const int he = y0 + ((ph + 1) * h + PH - 1) / PH;  // ceil
    const int ws = x0 + (pw * w) / PW;
    const int we = x0 + ((pw + 1) * w + PW - 1) / PW;

    const float* base = g_fmT + (size_t)b * HW * C_ + cg * 64 + 2 * lane;

    float2 acc = make_float2(-FLT_MAX, -FLT_MAX);
    for (int y = hs; y < he; ++y) {
        const float* rowp = base + (size_t)(y * W_) * C_;
        for (int x = ws; x < we; ++x) {
            float2 a = __ldg((const float2*)(rowp + (size_t)x * C_));
            acc.x = fmaxf(acc.x, a.x);
            acc.y = fmaxf(acc.y, a.y);
        }
    }

    so[(2 * lane) * PW + pw]     = acc.x;
    so[(2 * lane + 1) * PW + pw] = acc.y;
    __syncthreads();

    // out[r][cg*64 + c_local][ph][pw]; 448 floats, 2 iters per thread
    float* ob = out + ((size_t)r * C_ + cg * 64) * (PH * PW) + ph * PW;
    #pragma unroll
    for (int i = threadIdx.x; i < 64 * PW; i += 224) {
        int c  = i / PW;
        int pp = i - c * PW;
        ob[c * (PH * PW) + pp] = so[i];
    }
}

extern "C" void kernel_launch(void* const* d_in, const int* in_sizes, int n_in,
                              void* d_out, int out_size) {
    const float* fm   = (const float*)d_in[0];
    const float* rois = (const float*)d_in[1];
    float* out = (float*)d_out;

    int R = in_sizes[1] / 5;               // 300

    dim3 tgrid((HW + 63) / 64, C_ / 32, B_);   // 40 x 8 x 4
    transpose_kernel<<<tgrid, dim3(32, 8)>>>(fm);

    dim3 pgrid(PH, R, 4);                  // 7 x 300 x 4
    roi_pool_kernel<<<pgrid, 224>>>(rois, out);
}

// round 11
// speedup vs baseline: 1.3341x; 1.1140x over previous
#include <cuda_runtime.h>
#include <float.h>

// fm [B=4, C=256, H=50, W=50] f32, rois [R=300,5] f32 -> out [R,256,7,7] f32.
#define PH 7
#define PW 7
#define B_ 4
#define C_ 256
#define H_ 50
#define W_ 50
#define HW (H_ * W_)
#define C4 (C_ / 4)                    // row length in float4 units

// channels-last scratch: fmT[b][y][x][c]  (10.24 MB)
__device__ float g_fmT[B_ * HW * C_];

__device__ __forceinline__ int clampi(int v, int lo, int hi) {
    return min(max(v, lo), hi);
}

// [256, 2500] -> [2500, 256] transpose per batch, 32c x 64hw tiles. (validated)
__global__ __launch_bounds__(256) void transpose_kernel(
        const float* __restrict__ in) {
    __shared__ float tile[32][65];
    const int b   = blockIdx.z;
    const int hw0 = blockIdx.x * 64;
    const int c0  = blockIdx.y * 32;
    const int tx  = threadIdx.x;          // 32
    const int ty  = threadIdx.y;          // 8

    #pragma unroll
    for (int j = 0; j < 4; ++j) {
        const int cl = ty + j * 8;
        const float* src = in + (size_t)(b * C_ + c0 + cl) * HW;
        int hw = hw0 + tx;
        if (hw < HW)      tile[cl][tx]      = src[hw];
        hw = hw0 + 32 + tx;
        if (hw < HW)      tile[cl][tx + 32] = src[hw];
    }
    __syncthreads();
    #pragma unroll
    for (int j = 0; j < 8; ++j) {
        const int hwl = ty + j * 8;
        const int hw  = hw0 + hwl;
        if (hw < HW)
            g_fmT[(size_t)(b * HW + hw) * C_ + c0 + tx] = tile[tx][hwl];
    }
}

// Block = (ph, roi, 128-channel half). Warp = pw bin, lane = float4 quad
// (warp-load = 128 consecutive channels = 512B dense). ~12 independent
// float4 loads per thread. Results staged in smem, stored in NCHW.
__global__ __launch_bounds__(224) void roi_pool_kernel(
        const float* __restrict__ rois, float* __restrict__ out) {
    __shared__ float so[128 * PW];         // [c_local*7 + pw], 3.5 KB

    const int ph   = blockIdx.x;
    const int r    = blockIdx.y;
    const int half = blockIdx.z;           // 0..1 (128 channels each)
    const int lane = threadIdx.x & 31;
    const int pw   = threadIdx.x >> 5;     // 0..6

    // ---- ROI box (block-uniform; jnp.round == rintf under RN) ----
    const float* rp = rois + r * 5;
    const int b  = (int)__ldg(rp + 4);                 // float truncation
    int x0 = clampi((int)rintf(__ldg(rp + 0)), 0, W_ - 1);
    int x1 = clampi((int)rintf(__ldg(rp + 2)), 0, W_ - 1);
    int y0 = clampi((int)rintf(__ldg(rp + 1)), 0, H_ - 1);
    int y1 = clampi((int)rintf(__ldg(rp + 3)), 0, H_ - 1);
    x1 = max(x1, x0 + 1);                  // edges may reach 50; reads <= 49
    y1 = max(y1, y0 + 1);
    const int w = x1 - x0;                 // 1..49
    const int h = y1 - y0;

    const int hs = y0 + (ph * h) / PH;
    const int he = y0 + ((ph + 1) * h + PH - 1) / PH;  // ceil
    const int ws = x0 + (pw * w) / PW;
    const int we = x0 + ((pw + 1) * w + PW - 1) / PW;

    // float4 view of fmT; quad index within row = half*32 + lane
    const float4* f4 = (const float4*)g_fmT;
    const float4* base = f4 + ((size_t)b * HW) * C4 + half * 32 + lane;

    float4 acc = make_float4(-FLT_MAX, -FLT_MAX, -FLT_MAX, -FLT_MAX);
    for (int y = hs; y < he; ++y) {
        const float4* rowp = base + (size_t)(y * W_) * C4;
        #pragma unroll 4
        for (int x = ws; x < we; ++x) {
            float4 a = __ldg(rowp + (size_t)x * C4);
            acc.x = fmaxf(acc.x, a.x);
            acc.y = fmaxf(acc.y, a.y);
            acc.z = fmaxf(acc.z, a.z);
            acc.w = fmaxf(acc.w, a.w);
        }
    }

    // stage: channels 4*lane .. 4*lane+3 (local), bin pw
    so[(4 * lane + 0) * PW + pw] = acc.x;
    so[(4 * lane + 1) * PW + pw] = acc.y;
    so[(4 * lane + 2) * PW + pw] = acc.z;
    so[(4 * lane + 3) * PW + pw] = acc.w;
    __syncthreads();

    // out[r][half*128 + c_local][ph][pw]; 896 floats, 4 iters per thread
    float* ob = out + ((size_t)r * C_ + half * 128) * (PH * PW) + ph * PW;
    #pragma unroll
    for (int i = threadIdx.x; i < 128 * PW; i += 224) {
        int c  = i / PW;
        int pp = i - c * PW;
        ob[c * (PH * PW) + pp] = so[i];
    }
}

extern "C" void kernel_launch(void* const* d_in, const int* in_sizes, int n_in,
                              void* d_out, int out_size) {
    const float* fm   = (const float*)d_in[0];
    const float* rois = (const float*)d_in[1];
    float* out = (float*)d_out;

    int R = in_sizes[1] / 5;               // 300

    dim3 tgrid((HW + 63) / 64, C_ / 32, B_);   // 40 x 8 x 4
    transpose_kernel<<<tgrid, dim3(32, 8)>>>(fm);

    dim3 pgrid(PH, R, 2);                  // 7 x 300 x 2
    roi_pool_kernel<<<pgrid, 224>>>(rois, out);
}